// round 1
// baseline (speedup 1.0000x reference)
#include <cuda_runtime.h>
#include <math.h>

#define B_   8
#define C_   64
#define H_   256
#define W_   256
#define LD_  8
#define MEM_ 128
#define NROWS_ (B_ * W_)   // 2048

// Scratch (allocation-free per harness rules)
__device__ float g_y[NROWS_ * C_];     // pooled means, [row][c]
__device__ float g_gate[NROWS_ * C_];  // sigmoid gate * mu, [row][c]

// ---------------------------------------------------------------------------
// Kernel 1: mean over H for each (b, c, w). One block per (b,c) plane.
// Thread w walks h with stride W (each h-step is a fully coalesced 128B/warp).
// ---------------------------------------------------------------------------
__global__ __launch_bounds__(W_) void reduce_h_kernel(const float* __restrict__ x) {
    const int bc = blockIdx.x;            // 0 .. B*C-1
    const int b  = bc / C_;
    const int c  = bc % C_;
    const int w  = threadIdx.x;           // 0 .. 255

    const float* xp = x + (size_t)bc * (H_ * W_) + w;
    float s = 0.f;
#pragma unroll 8
    for (int h = 0; h < H_; ++h)
        s += xp[(size_t)h * W_];

    g_y[((size_t)b * W_ + w) * C_ + c] = s * (1.0f / H_);
}

// ---------------------------------------------------------------------------
// Kernel 2: per-row gating MLP + memory-bank attention. Warp per row.
// low = y @ w_sub + b_sub              (64 -> 8)
// f   = softmax(low @ mb * ld^-0.5)    (8 -> 128)
// y1  = f @ mb^T                       (128 -> 8)
// gate= sigmoid(y1 @ w_up + b_up) * mu (8 -> 64)
// ---------------------------------------------------------------------------
__global__ __launch_bounds__(256) void gate_kernel(
    const float* __restrict__ w_sub, const float* __restrict__ b_sub,
    const float* __restrict__ w_up,  const float* __restrict__ b_up,
    const float* __restrict__ mb,    const float* __restrict__ mu)
{
    __shared__ float s_wsub[C_ * LD_];    // 512
    __shared__ float s_mb[LD_ * MEM_];    // 1024
    __shared__ float s_wup[LD_ * C_];     // 512
    __shared__ float s_bsub[LD_];
    __shared__ float s_bup[C_];

    const int tid = threadIdx.x;
    for (int i = tid; i < C_ * LD_;   i += blockDim.x) s_wsub[i] = w_sub[i];
    for (int i = tid; i < LD_ * MEM_; i += blockDim.x) s_mb[i]   = mb[i];
    for (int i = tid; i < LD_ * C_;   i += blockDim.x) s_wup[i]  = w_up[i];
    if (tid < LD_) s_bsub[tid] = b_sub[tid];
    if (tid < C_)  s_bup[tid]  = b_up[tid];
    __syncthreads();

    const float muv = mu[0];
    const int warp = tid >> 5;
    const int lane = tid & 31;
    const int row  = blockIdx.x * (blockDim.x >> 5) + warp;
    if (row >= NROWS_) return;

    const float* yr = g_y + (size_t)row * C_;

    // low[0..7] — computed redundantly per lane (512 FMA, trivial)
    float low[LD_];
#pragma unroll
    for (int j = 0; j < LD_; ++j) low[j] = s_bsub[j];
#pragma unroll 4
    for (int c = 0; c < C_; ++c) {
        const float yv = yr[c];
#pragma unroll
        for (int j = 0; j < LD_; ++j)
            low[j] = fmaf(yv, s_wsub[c * LD_ + j], low[j]);
    }

    // f1 over mem=128: lane owns m = lane + 32*k, k=0..3
    const float scale = rsqrtf((float)LD_);
    float f1[4];
#pragma unroll
    for (int k = 0; k < 4; ++k) {
        const int m = lane + 32 * k;
        float acc = 0.f;
#pragma unroll
        for (int j = 0; j < LD_; ++j)
            acc = fmaf(low[j], s_mb[j * MEM_ + m], acc);
        f1[k] = acc * scale;
    }

    // softmax over 128 (4 locals x warp)
    float mx = fmaxf(fmaxf(f1[0], f1[1]), fmaxf(f1[2], f1[3]));
#pragma unroll
    for (int off = 16; off > 0; off >>= 1)
        mx = fmaxf(mx, __shfl_xor_sync(0xffffffffu, mx, off));
    float e[4], sum = 0.f;
#pragma unroll
    for (int k = 0; k < 4; ++k) { e[k] = expf(f1[k] - mx); sum += e[k]; }
#pragma unroll
    for (int off = 16; off > 0; off >>= 1)
        sum += __shfl_xor_sync(0xffffffffu, sum, off);
    const float inv = 1.0f / sum;

    // y1[j] = sum_m f[m] * mb[j][m]
    float y1[LD_];
#pragma unroll
    for (int j = 0; j < LD_; ++j) {
        float acc = 0.f;
#pragma unroll
        for (int k = 0; k < 4; ++k)
            acc = fmaf(e[k] * inv, s_mb[j * MEM_ + lane + 32 * k], acc);
#pragma unroll
        for (int off = 16; off > 0; off >>= 1)
            acc += __shfl_xor_sync(0xffffffffu, acc, off);
        y1[j] = acc;
    }

    // gate[c] for c = lane, lane+32
#pragma unroll
    for (int k = 0; k < 2; ++k) {
        const int c = lane + 32 * k;
        float acc = s_bup[c];
#pragma unroll
        for (int j = 0; j < LD_; ++j)
            acc = fmaf(y1[j], s_wup[j * C_ + c], acc);
        const float g = 1.0f / (1.0f + expf(-acc));
        g_gate[(size_t)row * C_ + c] = g * muv;
    }
}

// ---------------------------------------------------------------------------
// Kernel 3: out = x * gate(b,w,c). One block per (b,c) plane; gate values for
// all 256 w staged in shared, then float4 streaming multiply.
// ---------------------------------------------------------------------------
__global__ __launch_bounds__(256) void apply_gate_kernel(
    const float* __restrict__ x, float* __restrict__ out)
{
    const int bc = blockIdx.x;
    const int b  = bc / C_;
    const int c  = bc % C_;

    __shared__ float g[W_];
    for (int w = threadIdx.x; w < W_; w += blockDim.x)
        g[w] = g_gate[((size_t)b * W_ + w) * C_ + c];
    __syncthreads();

    const float4* __restrict__ xp = (const float4*)(x   + (size_t)bc * (H_ * W_));
    float4*       __restrict__ op = (float4*)      (out + (size_t)bc * (H_ * W_));

    const int n4 = (H_ * W_) / 4;       // 16384
#pragma unroll 4
    for (int i = threadIdx.x; i < n4; i += blockDim.x) {
        float4 v = xp[i];
        const int w4 = (i & (W_ / 4 - 1)) << 2;   // w offset of this float4
        v.x *= g[w4 + 0];
        v.y *= g[w4 + 1];
        v.z *= g[w4 + 2];
        v.w *= g[w4 + 3];
        op[i] = v;
    }
}

extern "C" void kernel_launch(void* const* d_in, const int* in_sizes, int n_in,
                              void* d_out, int out_size) {
    const float* x     = (const float*)d_in[0];
    const float* w_sub = (const float*)d_in[1];
    const float* b_sub = (const float*)d_in[2];
    const float* w_up  = (const float*)d_in[3];
    const float* b_up  = (const float*)d_in[4];
    const float* mb    = (const float*)d_in[5];
    const float* mu    = (const float*)d_in[6];
    float* out = (float*)d_out;

    reduce_h_kernel<<<B_ * C_, W_>>>(x);
    gate_kernel<<<NROWS_ / 8, 256>>>(w_sub, b_sub, w_up, b_up, mb, mu);
    apply_gate_kernel<<<B_ * C_, 256>>>(x, out);
}

// round 2
// speedup vs baseline: 1.0726x; 1.0726x over previous
#include <cuda_runtime.h>
#include <math.h>

#define B_   8
#define C_   64
#define H_   256
#define W_   256
#define LD_  8
#define MEM_ 128
#define NROWS_ (B_ * W_)    // 2048
#define HCHUNK_ 64          // h rows per reduce block
#define NQ_ (H_ / HCHUNK_)  // 4 chunks per plane

// Scratch (allocation-free per harness rules)
__device__ float g_part[B_ * C_ * NQ_ * W_];  // per-chunk partial h-sums, [(bc*NQ+q)][w]  (2 MB)
__device__ float g_gateT[B_ * C_ * W_];       // gate*mu, transposed [bc][w]               (0.5 MB)

// ---------------------------------------------------------------------------
// Kernel 1: partial sum over a 64-row h-chunk of one (b,c) plane.
// 2048 blocks x 256 threads; float4 loads; shared combine across 4 h-subgroups.
// ---------------------------------------------------------------------------
__global__ __launch_bounds__(256) void reduce_h_partial_kernel(const float* __restrict__ x) {
    const int bcq = blockIdx.x;           // 0 .. B*C*NQ-1
    const int bc  = bcq >> 2;
    const int q   = bcq & (NQ_ - 1);

    const int t  = threadIdx.x;
    const int w4 = t & 63;                // float4 column 0..63
    const int hs = t >> 6;                // h-subgroup 0..3

    const float4* __restrict__ xp =
        (const float4*)(x + (size_t)bc * (H_ * W_) + (size_t)q * HCHUNK_ * W_);

    float4 s = make_float4(0.f, 0.f, 0.f, 0.f);
    // thread covers h = hs + 4k, k = 0..15 within the chunk; each iter coalesced 1KB/row-group
#pragma unroll
    for (int k = 0; k < HCHUNK_ / 4; ++k) {
        float4 v = xp[(size_t)(hs + 4 * k) * (W_ / 4) + w4];
        s.x += v.x; s.y += v.y; s.z += v.z; s.w += v.w;
    }

    __shared__ float4 red[256];
    red[t] = s;
    __syncthreads();
    if (hs == 0) {
        float4 a = red[t], b1 = red[t + 64], c1 = red[t + 128], d = red[t + 192];
        a.x += b1.x + c1.x + d.x;
        a.y += b1.y + c1.y + d.y;
        a.z += b1.z + c1.z + d.z;
        a.w += b1.w + c1.w + d.w;
        ((float4*)g_part)[(size_t)bcq * (W_ / 4) + w4] = a;   // coalesced
    }
}

// ---------------------------------------------------------------------------
// Kernel 2: per-row gating MLP + memory-bank attention. Warp per row (b,w).
// Combines the NQ_ h-partials into the pooled mean on the fly.
// Writes gate transposed: g_gateT[(b*C+c)*W + w].
// ---------------------------------------------------------------------------
__global__ __launch_bounds__(256) void gate_kernel(
    const float* __restrict__ w_sub, const float* __restrict__ b_sub,
    const float* __restrict__ w_up,  const float* __restrict__ b_up,
    const float* __restrict__ mb,    const float* __restrict__ mu)
{
    __shared__ float s_wsub[C_ * LD_];
    __shared__ float s_mb[LD_ * MEM_];
    __shared__ float s_wup[LD_ * C_];
    __shared__ float s_bsub[LD_];
    __shared__ float s_bup[C_];

    const int tid = threadIdx.x;
    for (int i = tid; i < C_ * LD_;   i += blockDim.x) s_wsub[i] = w_sub[i];
    for (int i = tid; i < LD_ * MEM_; i += blockDim.x) s_mb[i]   = mb[i];
    for (int i = tid; i < LD_ * C_;   i += blockDim.x) s_wup[i]  = w_up[i];
    if (tid < LD_) s_bsub[tid] = b_sub[tid];
    if (tid < C_)  s_bup[tid]  = b_up[tid];
    __syncthreads();

    const float muv = mu[0];
    const int warp = tid >> 5;
    const int lane = tid & 31;
    const int row  = blockIdx.x * (blockDim.x >> 5) + warp;
    if (row >= NROWS_) return;

    const int b = row / W_;
    const int w = row % W_;

    // low = y @ w_sub + b_sub, with y[c] reconstructed from the 4 h-partials.
    // Loads are lane-uniform (broadcast) — cheap.
    float low[LD_];
#pragma unroll
    for (int j = 0; j < LD_; ++j) low[j] = s_bsub[j];

    const float inv_h = 1.0f / H_;
#pragma unroll 4
    for (int c = 0; c < C_; ++c) {
        const float* pp = g_part + ((size_t)(b * C_ + c) * NQ_) * W_ + w;
        const float yv = (pp[0] + pp[W_] + pp[2 * W_] + pp[3 * W_]) * inv_h;
#pragma unroll
        for (int j = 0; j < LD_; ++j)
            low[j] = fmaf(yv, s_wsub[c * LD_ + j], low[j]);
    }

    // f1 over mem=128: lane owns m = lane + 32k
    const float scale = rsqrtf((float)LD_);
    float f1[4];
#pragma unroll
    for (int k = 0; k < 4; ++k) {
        const int m = lane + 32 * k;
        float acc = 0.f;
#pragma unroll
        for (int j = 0; j < LD_; ++j)
            acc = fmaf(low[j], s_mb[j * MEM_ + m], acc);
        f1[k] = acc * scale;
    }

    // softmax over 128
    float mx = fmaxf(fmaxf(f1[0], f1[1]), fmaxf(f1[2], f1[3]));
#pragma unroll
    for (int off = 16; off > 0; off >>= 1)
        mx = fmaxf(mx, __shfl_xor_sync(0xffffffffu, mx, off));
    float e[4], sum = 0.f;
#pragma unroll
    for (int k = 0; k < 4; ++k) { e[k] = expf(f1[k] - mx); sum += e[k]; }
#pragma unroll
    for (int off = 16; off > 0; off >>= 1)
        sum += __shfl_xor_sync(0xffffffffu, sum, off);
    const float inv = 1.0f / sum;

    // y1[j] = sum_m f[m] * mb[j][m]
    float y1[LD_];
#pragma unroll
    for (int j = 0; j < LD_; ++j) {
        float acc = 0.f;
#pragma unroll
        for (int k = 0; k < 4; ++k)
            acc = fmaf(e[k] * inv, s_mb[j * MEM_ + lane + 32 * k], acc);
#pragma unroll
        for (int off = 16; off > 0; off >>= 1)
            acc += __shfl_xor_sync(0xffffffffu, acc, off);
        y1[j] = acc;
    }

    // gate[c] for c = lane, lane+32 ; write transposed [bc][w]
#pragma unroll
    for (int k = 0; k < 2; ++k) {
        const int c = lane + 32 * k;
        float acc = s_bup[c];
#pragma unroll
        for (int j = 0; j < LD_; ++j)
            acc = fmaf(y1[j], s_wup[j * C_ + c], acc);
        const float g = 1.0f / (1.0f + expf(-acc));
        g_gateT[(size_t)(b * C_ + c) * W_ + w] = g * muv;
    }
}

// ---------------------------------------------------------------------------
// Kernel 3: out = x * gate. 2048 blocks, each handles a 64-row h-chunk of one
// (b,c) plane. Gate staged in shared (coalesced from transposed layout).
// ---------------------------------------------------------------------------
__global__ __launch_bounds__(256) void apply_gate_kernel(
    const float* __restrict__ x, float* __restrict__ out)
{
    const int bcq = blockIdx.x;
    const int bc  = bcq >> 2;
    const int q   = bcq & (NQ_ - 1);

    __shared__ float g[W_];
    for (int w = threadIdx.x; w < W_; w += blockDim.x)
        g[w] = g_gateT[(size_t)bc * W_ + w];          // fully coalesced
    __syncthreads();

    const size_t base = (size_t)bc * (H_ * W_) + (size_t)q * HCHUNK_ * W_;
    const float4* __restrict__ xp = (const float4*)(x + base);
    float4*       __restrict__ op = (float4*)(out + base);

    const int n4 = HCHUNK_ * W_ / 4;      // 4096
#pragma unroll 4
    for (int i = threadIdx.x; i < n4; i += 256) {
        float4 v = xp[i];
        const int w4 = (i & (W_ / 4 - 1)) << 2;
        v.x *= g[w4 + 0];
        v.y *= g[w4 + 1];
        v.z *= g[w4 + 2];
        v.w *= g[w4 + 3];
        op[i] = v;
    }
}

extern "C" void kernel_launch(void* const* d_in, const int* in_sizes, int n_in,
                              void* d_out, int out_size) {
    const float* x     = (const float*)d_in[0];
    const float* w_sub = (const float*)d_in[1];
    const float* b_sub = (const float*)d_in[2];
    const float* w_up  = (const float*)d_in[3];
    const float* b_up  = (const float*)d_in[4];
    const float* mb    = (const float*)d_in[5];
    const float* mu    = (const float*)d_in[6];
    float* out = (float*)d_out;

    reduce_h_partial_kernel<<<B_ * C_ * NQ_, 256>>>(x);
    gate_kernel<<<NROWS_ / 8, 256>>>(w_sub, b_sub, w_up, b_up, mb, mu);
    apply_gate_kernel<<<B_ * C_ * NQ_, 256>>>(x, out);
}

// round 3
// speedup vs baseline: 1.1105x; 1.0353x over previous
#include <cuda_runtime.h>
#include <math.h>

#define B_   8
#define C_   64
#define H_   256
#define W_   256
#define LD_  8
#define MEM_ 128
#define NROWS_ (B_ * W_)    // 2048
#define HCHUNK_ 64          // h rows per reduce block
#define NQ_ (H_ / HCHUNK_)  // 4 chunks per plane
#define NBLK_ (B_ * C_ * NQ_)  // 2048

// Scratch (allocation-free per harness rules)
__device__ float g_part[B_ * C_ * NQ_ * W_];  // per-chunk partial h-sums  (2 MB)
__device__ float g_gateT[B_ * C_ * W_];       // gate*mu, transposed [bc][w] (0.5 MB)

// ---------------------------------------------------------------------------
// Kernel 1: partial sum over a 64-row h-chunk of one (b,c) plane.
// Default-cached reads: we WANT x resident in L2 for kernel 3.
// ---------------------------------------------------------------------------
__global__ __launch_bounds__(256) void reduce_h_partial_kernel(const float* __restrict__ x) {
    const int bcq = blockIdx.x;           // 0 .. NBLK_-1
    const int bc  = bcq >> 2;
    const int q   = bcq & (NQ_ - 1);

    const int t  = threadIdx.x;
    const int w4 = t & 63;                // float4 column 0..63
    const int hs = t >> 6;                // h-subgroup 0..3

    const float4* __restrict__ xp =
        (const float4*)(x + (size_t)bc * (H_ * W_) + (size_t)q * HCHUNK_ * W_);

    float4 s = make_float4(0.f, 0.f, 0.f, 0.f);
#pragma unroll
    for (int k = 0; k < HCHUNK_ / 4; ++k) {
        float4 v = xp[(size_t)(hs + 4 * k) * (W_ / 4) + w4];
        s.x += v.x; s.y += v.y; s.z += v.z; s.w += v.w;
    }

    __shared__ float4 red[256];
    red[t] = s;
    __syncthreads();
    if (hs == 0) {
        float4 a = red[t], b1 = red[t + 64], c1 = red[t + 128], d = red[t + 192];
        a.x += b1.x + c1.x + d.x;
        a.y += b1.y + c1.y + d.y;
        a.z += b1.z + c1.z + d.z;
        a.w += b1.w + c1.w + d.w;
        // streaming store: don't displace x from L2
        __stcs(&((float4*)g_part)[(size_t)bcq * (W_ / 4) + w4], a);
    }
}

// ---------------------------------------------------------------------------
// Kernel 2: per-row gating MLP + memory-bank attention. Warp per row (b,w).
// ---------------------------------------------------------------------------
__global__ __launch_bounds__(256) void gate_kernel(
    const float* __restrict__ w_sub, const float* __restrict__ b_sub,
    const float* __restrict__ w_up,  const float* __restrict__ b_up,
    const float* __restrict__ mb,    const float* __restrict__ mu)
{
    __shared__ float s_wsub[C_ * LD_];
    __shared__ float s_mb[LD_ * MEM_];
    __shared__ float s_wup[LD_ * C_];
    __shared__ float s_bsub[LD_];
    __shared__ float s_bup[C_];

    const int tid = threadIdx.x;
    for (int i = tid; i < C_ * LD_;   i += blockDim.x) s_wsub[i] = w_sub[i];
    for (int i = tid; i < LD_ * MEM_; i += blockDim.x) s_mb[i]   = mb[i];
    for (int i = tid; i < LD_ * C_;   i += blockDim.x) s_wup[i]  = w_up[i];
    if (tid < LD_) s_bsub[tid] = b_sub[tid];
    if (tid < C_)  s_bup[tid]  = b_up[tid];
    __syncthreads();

    const float muv = mu[0];
    const int warp = tid >> 5;
    const int lane = tid & 31;
    const int row  = blockIdx.x * (blockDim.x >> 5) + warp;
    if (row >= NROWS_) return;

    const int b = row / W_;
    const int w = row % W_;

    float low[LD_];
#pragma unroll
    for (int j = 0; j < LD_; ++j) low[j] = s_bsub[j];

    const float inv_h = 1.0f / H_;
#pragma unroll 4
    for (int c = 0; c < C_; ++c) {
        const float* pp = g_part + ((size_t)(b * C_ + c) * NQ_) * W_ + w;
        const float yv = (__ldcs(pp) + __ldcs(pp + W_) +
                          __ldcs(pp + 2 * W_) + __ldcs(pp + 3 * W_)) * inv_h;
#pragma unroll
        for (int j = 0; j < LD_; ++j)
            low[j] = fmaf(yv, s_wsub[c * LD_ + j], low[j]);
    }

    const float scale = rsqrtf((float)LD_);
    float f1[4];
#pragma unroll
    for (int k = 0; k < 4; ++k) {
        const int m = lane + 32 * k;
        float acc = 0.f;
#pragma unroll
        for (int j = 0; j < LD_; ++j)
            acc = fmaf(low[j], s_mb[j * MEM_ + m], acc);
        f1[k] = acc * scale;
    }

    float mx = fmaxf(fmaxf(f1[0], f1[1]), fmaxf(f1[2], f1[3]));
#pragma unroll
    for (int off = 16; off > 0; off >>= 1)
        mx = fmaxf(mx, __shfl_xor_sync(0xffffffffu, mx, off));
    float e[4], sum = 0.f;
#pragma unroll
    for (int k = 0; k < 4; ++k) { e[k] = expf(f1[k] - mx); sum += e[k]; }
#pragma unroll
    for (int off = 16; off > 0; off >>= 1)
        sum += __shfl_xor_sync(0xffffffffu, sum, off);
    const float inv = 1.0f / sum;

    float y1[LD_];
#pragma unroll
    for (int j = 0; j < LD_; ++j) {
        float acc = 0.f;
#pragma unroll
        for (int k = 0; k < 4; ++k)
            acc = fmaf(e[k] * inv, s_mb[j * MEM_ + lane + 32 * k], acc);
#pragma unroll
        for (int off = 16; off > 0; off >>= 1)
            acc += __shfl_xor_sync(0xffffffffu, acc, off);
        y1[j] = acc;
    }

#pragma unroll
    for (int k = 0; k < 2; ++k) {
        const int c = lane + 32 * k;
        float acc = s_bup[c];
#pragma unroll
        for (int j = 0; j < LD_; ++j)
            acc = fmaf(y1[j], s_wup[j * C_ + c], acc);
        const float g = 1.0f / (1.0f + expf(-acc));
        g_gateT[(size_t)(b * C_ + c) * W_ + w] = g * muv;
    }
}

// ---------------------------------------------------------------------------
// Kernel 3: out = x * gate. REVERSE block order so the tail of x (still L2-
// resident from kernel 1) is consumed first. Streaming loads/stores protect
// the residency window.
// ---------------------------------------------------------------------------
__global__ __launch_bounds__(256) void apply_gate_kernel(
    const float* __restrict__ x, float* __restrict__ out)
{
    const int bcq = (NBLK_ - 1) - blockIdx.x;   // reverse order for L2 reuse
    const int bc  = bcq >> 2;
    const int q   = bcq & (NQ_ - 1);

    __shared__ float g[W_];
    for (int w = threadIdx.x; w < W_; w += blockDim.x)
        g[w] = g_gateT[(size_t)bc * W_ + w];
    __syncthreads();

    const size_t base = (size_t)bc * (H_ * W_) + (size_t)q * HCHUNK_ * W_;
    const float4* __restrict__ xp = (const float4*)(x + base);
    float4*       __restrict__ op = (float4*)(out + base);

    const int n4 = HCHUNK_ * W_ / 4;      // 4096
#pragma unroll 8
    for (int i = threadIdx.x; i < n4; i += 256) {
        float4 v = __ldcs(&xp[i]);                 // evict-first: never reused
        const int w4 = (i & (W_ / 4 - 1)) << 2;
        v.x *= g[w4 + 0];
        v.y *= g[w4 + 1];
        v.z *= g[w4 + 2];
        v.w *= g[w4 + 3];
        __stcs(&op[i], v);                         // streaming store
    }
}

extern "C" void kernel_launch(void* const* d_in, const int* in_sizes, int n_in,
                              void* d_out, int out_size) {
    const float* x     = (const float*)d_in[0];
    const float* w_sub = (const float*)d_in[1];
    const float* b_sub = (const float*)d_in[2];
    const float* w_up  = (const float*)d_in[3];
    const float* b_up  = (const float*)d_in[4];
    const float* mb    = (const float*)d_in[5];
    const float* mu    = (const float*)d_in[6];
    float* out = (float*)d_out;

    reduce_h_partial_kernel<<<NBLK_, 256>>>(x);
    gate_kernel<<<NROWS_ / 8, 256>>>(w_sub, b_sub, w_up, b_up, mb, mu);
    apply_gate_kernel<<<NBLK_, 256>>>(x, out);
}